// round 15
// baseline (speedup 1.0000x reference)
#include <cuda_runtime.h>
#include <cuda_fp16.h>
#include <cstdint>

// lstm_model_8873402433789 R15 — thin-warp fp16 mma.sync LSTM, 4096 warps.
// Gate rows PERMUTED so warp w owns units 8w..8w+7 x {i,f,c,o} = 32 contiguous
// gate rows = 2 m-tiles -> 6 MMAs/warp-step, ~60 regs, 7 CTAs/SM (28 warps/SM).
// CTA = 128 thr / 8 batch rows; one __syncthreads per step; x staged shared.
// Row perm: gate(type t, unit u=8w'+j) -> 32w' + 16*(t>>1) + 8*(t&1) + j.

#define TT 200
#define DD 60
#define WSTR 56    // weight row stride (halfs), 112B
#define HSTR 40    // h row stride (halfs), 80B; [2 buf][8 rows][HSTR]
#define XSTR 40    // x row stride; buf0 cols 0-15, buf1 16-31

static __device__ __forceinline__ uint32_t s2u(const void* p) {
    uint32_t a;
    asm("{ .reg .u64 t; cvta.to.shared.u64 t, %1; cvt.u32.u64 %0, t; }"
        : "=r"(a) : "l"(p));
    return a;
}
static __device__ __forceinline__ uint32_t hpack(float lo, float hi) {
    __half2 t = __floats2half2_rn(lo, hi);
    return *(uint32_t*)&t;
}
static __device__ __forceinline__ __half2 tanh2(uint32_t g2) {
    uint32_t r;
    asm("tanh.approx.f16x2 %0, %1;" : "=r"(r) : "r"(g2));
    return *(__half2*)&r;
}
static __device__ __forceinline__ void ldsm4(uint32_t* r, uint32_t addr) {
    asm volatile("ldmatrix.sync.aligned.m8n8.x4.shared.b16 {%0,%1,%2,%3}, [%4];"
                 : "=r"(r[0]), "=r"(r[1]), "=r"(r[2]), "=r"(r[3]) : "r"(addr));
}
static __device__ __forceinline__ void ldsm2(uint32_t* r, uint32_t addr) {
    asm volatile("ldmatrix.sync.aligned.m8n8.x2.shared.b16 {%0,%1}, [%2];"
                 : "=r"(r[0]), "=r"(r[1]) : "r"(addr));
}
static __device__ __forceinline__ void mma16816(float* d, const uint32_t* a,
                                                const uint32_t* b) {
    asm volatile(
        "mma.sync.aligned.m16n8k16.row.col.f32.f16.f16.f32 "
        "{%0,%1,%2,%3}, {%4,%5,%6,%7}, {%8,%9}, {%0,%1,%2,%3};"
        : "+f"(d[0]), "+f"(d[1]), "+f"(d[2]), "+f"(d[3])
        : "r"(a[0]), "r"(a[1]), "r"(a[2]), "r"(a[3]), "r"(b[0]), "r"(b[1]));
}

__global__ void __launch_bounds__(128, 7) lstm_thin_kernel(
    const float* __restrict__ x,  const float* __restrict__ W,
    const float* __restrict__ U,  const float* __restrict__ b,
    const float* __restrict__ W1, const float* __restrict__ b1,
    const float* __restrict__ W2, const float* __restrict__ b2,
    float* __restrict__ out)
{
    __shared__ __align__(16) __half wsm[128 * WSTR];       // permuted weights
    __shared__ __align__(16) __half hsm[2 * 8 * HSTR];     // h, dbl buffered
    __shared__ __align__(16) __half xsm[8 * XSTR];         // x, dbl buf in-row

    const int tid = threadIdx.x;
    const int l   = tid & 31;
    const int w   = tid >> 5;        // warp 0..3: units 8w..8w+7
    const int gid = l >> 2, tig = l & 3;
    const int lr8 = l & 7;

    // ---- weights, gate rows permuted; 0.5 folded into i/f/o; K=[U 0-31|W 32-47]
    for (int idx = tid; idx < 128 * 48; idx += 128) {
        int g = idx / 48, k = idx - g * 48;
        int typ = g >> 5, u = g & 31;
        int row = 32 * (u >> 3) + 16 * (typ >> 1) + 8 * (typ & 1) + (u & 7);
        float src = (k < 32) ? U[k * 128 + g] : W[(k - 32) * 128 + g];
        float sc  = (typ == 2) ? 1.0f : 0.5f;
        wsm[row * WSTR + k] = __float2half_rn(src * sc);
    }
    __syncthreads();

    // ---- A fragments: afr[mtl 0=(i|f),1=(c|o)][ks 0,1=U k; 2=W x]
    const uint32_t wsmu = s2u(wsm);
    uint32_t afr[2][3][4];
    {
        int laneRow = lr8 + 8 * ((l >> 3) & 1);
        int laneK   = 8 * (l >> 4);
#pragma unroll
        for (int mtl = 0; mtl < 2; ++mtl)
#pragma unroll
            for (int ks = 0; ks < 3; ++ks)
                ldsm4(afr[mtl][ks],
                      wsmu + ((32 * w + 16 * mtl + laneRow) * WSTR + 16 * ks + laneK) * 2);
    }
    // biases for this thread's unit (i/f/o pre-halved)
    const int unit = 8 * w + gid;
    const float bi = 0.5f * b[unit],      bf = 0.5f * b[32 + unit];
    const float bc = b[64 + unit],        bo = 0.5f * b[96 + unit];

    // ---- zero h buf0; stage x(0); prefetch x(1) (1 float/thread/step)
    for (int idx = tid; idx < 8 * HSTR; idx += 128)
        hsm[idx] = __float2half_rn(0.0f);
    const int xrow = tid >> 4, xfeat = tid & 15;
    const float* xg = x + ((size_t)blockIdx.x * 8 + xrow) * (TT * 16) + xfeat;
    xsm[xrow * XSTR + xfeat] = __float2half_rn(xg[0]);
    float pf = xg[16];
    __syncthreads();

    const uint32_t hbu = s2u(hsm);
    const uint32_t xbu = s2u(xsm);
    const uint32_t xfoff = (lr8 * XSTR + 8 * ((l >> 3) & 1)) * 2;
    uint32_t xf[2];
    ldsm2(xf, xbu + xfoff);          // x(0)

    float cst[2] = {0.0f, 0.0f};

#pragma unroll 1
    for (int t = 0; t < TT; ++t) {
        const int p = t & 1, pn = p ^ 1;

        // ---- stage x(t+1) -> buf pn (pre-barrier); prefetch x(t+2)
        xsm[xrow * XSTR + pn * 16 + xfeat] = __float2half_rn(pf);
        {
            int tn = (t + 2 < TT) ? t + 2 : TT - 1;
            pf = xg[tn * 16];
        }

        // ---- x-MMAs with xf(t)
        float dac[2][4];
        dac[0][0] = bi; dac[0][1] = bi; dac[0][2] = bf; dac[0][3] = bf;
        dac[1][0] = bc; dac[1][1] = bc; dac[1][2] = bo; dac[1][3] = bo;
        mma16816(dac[0], afr[0][2], xf);
        mma16816(dac[1], afr[1][2], xf);

        // ---- barrier: h(t) from all warps + x(t+1) staged
        __syncthreads();

        // ---- h fragment (buf p) + xf(t+1) (buf pn), then h-MMAs
        uint32_t bh[4];
        ldsm4(bh, hbu + (p * (8 * HSTR) + lr8 * HSTR + 8 * (l >> 3)) * 2);
        ldsm2(xf, xbu + pn * 32 + xfoff);
        mma16816(dac[0], afr[0][0], &bh[0]);
        mma16816(dac[0], afr[0][1], &bh[2]);
        mma16816(dac[1], afr[1][0], &bh[0]);
        mma16816(dac[1], afr[1][1], &bh[2]);

        // ---- update: 2 batch elems, pairs already adjacent in D frags
        __half2 ti = tanh2(hpack(dac[0][0], dac[0][1]));
        __half2 tf = tanh2(hpack(dac[0][2], dac[0][3]));
        __half2 to = tanh2(hpack(dac[1][2], dac[1][3]));
#pragma unroll
        for (int q = 0; q < 2; ++q) {
            float tiq = q ? __high2float(ti) : __low2float(ti);
            float tfq = q ? __high2float(tf) : __low2float(tf);
            float toq = q ? __high2float(to) : __low2float(to);
            float cc  = fmaxf(dac[1][q], 0.0f);
            float co  = cst[q];
            float c   = 0.5f * (fmaf(tfq, co, co) + fmaf(tiq, cc, cc));
            cst[q] = c;
            float hv  = fmaf(0.5f, toq, 0.5f) * fmaxf(c, 0.0f);
            hsm[pn * (8 * HSTR) + (2 * tig + q) * HSTR + unit] = __float2half_rn(hv);
        }
        // next iteration's __syncthreads covers h/x visibility
    }

    // ---- output heads: final h in hsm buf0 (t=200 even), fp16 -> fp32
    __syncthreads();
    for (int idx = tid; idx < 8 * DD; idx += 128) {
        int rr = idx / DD, d = idx - rr * DD;
        const __half* hr = hsm + rr * HSTR;
        float aL = b1[d], aA = b2[d];
#pragma unroll
        for (int u = 0; u < 32; ++u) {
            float hu = __half2float(hr[u]);
            aL = fmaf(hu, W1[u * DD + d], aL);
            aA = fmaf(hu, W2[u * DD + d], aA);
        }
        size_t grow = (size_t)blockIdx.x * 8 + rr;
        out[grow * DD + d] = aL;
        out[(8192 + grow) * DD + d] = aA;
    }
}

extern "C" void kernel_launch(void* const* d_in, const int* in_sizes, int n_in,
                              void* d_out, int out_size) {
    const float* x  = (const float*)d_in[0];
    const float* W  = (const float*)d_in[1];
    const float* U  = (const float*)d_in[2];
    const float* b  = (const float*)d_in[3];
    const float* W1 = (const float*)d_in[4];
    const float* b1 = (const float*)d_in[5];
    const float* W2 = (const float*)d_in[6];
    const float* b2 = (const float*)d_in[7];
    float* out = (float*)d_out;

    // 8192 rows / 8 per CTA = 1024 CTAs x 128 thr (4 thin warps)
    lstm_thin_kernel<<<1024, 128>>>(x, W, U, b, W1, b1, W2, b2, out);
}